// round 10
// baseline (speedup 1.0000x reference)
#include <cuda_runtime.h>

// ----------------------------------------------------------------------------
// LSTM autoencoder, fp32, FFMA2 + 8-row x 8-col register tile, NT=256.
// B=65536, T=8, D=60, H=128, L=64. PyTorch gate order i,f,g,o.
//
// Per CTA: M=32 batch rows, 256 threads (8 warps). Warp ty: row group
// rg=ty>>1 (rows r0=8*rg..+7), column half ch=ty&1. Thread owns gate columns
// {64*ch + 2*tx + e + 128*j : e=0..1, j=0..3} -> acc = 32 u64 (64 regs),
// weight smem traffic 0.5 B/FMA (vs 1.0 in the 4x16 tile) with only a
// 4x16-sized accumulator footprint -> 2 CTAs/SM (16 warps) AND crossbar relief.
// Weights staged transposed (Wt[kk][c], pitch 512) in 16-k chunks, read as
// conflict-free LDS.64 (lane stride 8B); activations broadcast float2 per 2-k.
// c-state in registers (16); h-state in smem (float2 I/O). DBUF=1 double-
// buffers weight staging.
// MODE 0: write h sequence; MODE 1: z = h_last@W_lat^T+b; MODE 2: per-t
// projection out_t = h_t@W_out^T+b (conflict-free pitch-132 float4 epilogue).
// ----------------------------------------------------------------------------

typedef unsigned long long u64;

#define CB 65536
#define CT 8
#define CD 60
#define CH 128
#define CL 64
#define MR 32
#define NT 256

__device__ float g_h1[(size_t)CB * CT * CH]; // 256 MB
__device__ float g_d1[(size_t)CB * CT * CH]; // 256 MB
__device__ float g_z [(size_t)CB * CL];      // 16 MB

__device__ __forceinline__ float sigf(float x)     { return 1.f / (1.f + __expf(-x)); }
__device__ __forceinline__ float tanhfast(float x) { return 2.f / (1.f + __expf(-2.f * x)) - 1.f; }

__device__ __forceinline__ void ffma2(u64& d, u64 a, u64 b) {
    asm("fma.rn.f32x2 %0, %1, %2, %0;" : "+l"(d) : "l"(a), "l"(b));
}
__device__ __forceinline__ u64 pack2(float x) {
    u64 v; asm("mov.b64 %0, {%1, %1};" : "=l"(v) : "f"(x)); return v;
}
__device__ __forceinline__ float2 unpack2(u64 v) {
    float2 f; asm("mov.b64 {%0, %1}, %2;" : "=f"(f.x), "=f"(f.y) : "l"(v)); return f;
}

// stage one 16-k chunk of W [512 x KD] row-major into Wt[kk][c] (pitch 512),
// transposed via float4 global reads. NT=256: kt=tid&3 (k-group), cb=tid>>2.
template <int KD>
__device__ __forceinline__ void stage_chunk(const float* __restrict__ W, int ci,
                                            float* __restrict__ Wt, int tid)
{
    const int k0   = 16 * ci;
    const int klen = (KD - k0 < 16) ? (KD - k0) : 16;
    const int kt   = tid & 3;
    const int cb   = tid >> 2;  // 0..63
    if (kt * 4 < klen) {
#pragma unroll
        for (int w = 0; w < 8; ++w) {
            int c = cb + 64 * w;
            float4 g = *(const float4*)(W + (size_t)c * KD + k0 + 4 * kt);
            float* d = Wt + 4 * kt * 512 + c;
            d[0] = g.x; d[512] = g.y; d[1024] = g.z; d[1536] = g.w;
        }
    }
}

// compute one staged chunk: act rows r0..r0+7 (this thread), nk2 groups of 2 k.
// cb0 = 64*ch + 2*tx : this thread's column pair base within each gate.
__device__ __forceinline__ void gemm_chunk2(const float* __restrict__ act, int pitch,
                                            const float* __restrict__ Wt, int cb0,
                                            u64 (&acc)[8][4], int nk2)
{
    for (int q = 0; q < nk2; ++q) {
        float2 a[8];
#pragma unroll
        for (int r = 0; r < 8; ++r)
            a[r] = *(const float2*)(act + r * pitch + 2 * q);
#pragma unroll
        for (int kk = 0; kk < 2; ++kk) {
            const float* wb = Wt + (2 * q + kk) * 512 + cb0;
            u64 w0 = *(const u64*)(wb);
            u64 w1 = *(const u64*)(wb + 128);
            u64 w2 = *(const u64*)(wb + 256);
            u64 w3 = *(const u64*)(wb + 384);
#pragma unroll
            for (int r = 0; r < 8; ++r) {
                u64 p = pack2(kk ? a[r].y : a[r].x);
                ffma2(acc[r][0], p, w0);
                ffma2(acc[r][1], p, w1);
                ffma2(acc[r][2], p, w2);
                ffma2(acc[r][3], p, w3);
            }
        }
    }
}

// one full GEMM pass over weights W [512 x KD] against act (pitch given).
template <int KD, int DBUF>
__device__ __forceinline__ void gemm_pass(const float* __restrict__ W,
                                          const float* __restrict__ act, int pitch,
                                          float* __restrict__ Wt0, float* __restrict__ Wt1,
                                          int tid, int cb0, u64 (&acc)[8][4])
{
    constexpr int NCH = (KD + 15) >> 4;
    if (DBUF) {
        stage_chunk<KD>(W, 0, Wt0, tid);
        __syncthreads();
#pragma unroll
        for (int ci = 0; ci < NCH; ++ci) {
            float* cw = (ci & 1) ? Wt1 : Wt0;
            float* nw = (ci & 1) ? Wt0 : Wt1;
            if (ci + 1 < NCH) stage_chunk<KD>(W, ci + 1, nw, tid);
            const int klen = (KD - 16 * ci < 16) ? (KD - 16 * ci) : 16;
            gemm_chunk2(act + 16 * ci, pitch, cw, cb0, acc, klen >> 1);
            __syncthreads();
        }
    } else {
#pragma unroll
        for (int ci = 0; ci < NCH; ++ci) {
            __syncthreads();                 // prior consumers of Wt0 done
            stage_chunk<KD>(W, ci, Wt0, tid);
            __syncthreads();
            const int klen = (KD - 16 * ci < 16) ? (KD - 16 * ci) : 16;
            gemm_chunk2(act + 16 * ci, pitch, Wt0, cb0, acc, klen >> 1);
        }
    }
}

template <int DIN, int MODE, int BCAST, int DBUF>
__global__ __launch_bounds__(NT, 2)
void lstm_kernel(const float* __restrict__ X,
                 const float* __restrict__ Wih, const float* __restrict__ Whh,
                 const float* __restrict__ bih, const float* __restrict__ bhh,
                 const float* __restrict__ Waux, const float* __restrict__ baux,
                 float* __restrict__ OutSeq, float* __restrict__ OutAux)
{
    constexpr int XP = (DIN + 3) & ~3;       // padded act pitch (60/64/128)
    extern __shared__ float sm[];
    float* Hbuf   = sm;                       // 4096
    float* Xbuf   = sm + 4096;                // 32*XP
    float* bias_s = Xbuf + MR * XP;           // 512
    float* Wt0    = bias_s + 512;             // 8192
    float* Wt1    = DBUF ? (Wt0 + 8192) : Wt0;
    float* Waux_s = Wt0 + (DBUF ? 16384 : 8192); // MODE2: 60*132 = 7920

    const int tid = threadIdx.x;
    const int tx  = tid & 31;
    const int ty  = tid >> 5;                 // 0..7
    const int r0  = (ty >> 1) * 8;            // row group base
    const int cb0 = (ty & 1) * 64 + 2 * tx;   // column pair base within a gate
    const int rowbase = blockIdx.x * MR;

    for (int i = tid; i < 512; i += NT) bias_s[i] = bih[i] + bhh[i];
    if (MODE == 2) {
        for (int i = tid; i < CD * CH; i += NT) {
            int c = i >> 7, k = i & 127;
            Waux_s[c * 132 + k] = Waux[i];
        }
    }
    if (BCAST) {
        constexpr int VPR = DIN / 4;
        for (int i = tid; i < MR * VPR; i += NT) {
            int r = i / VPR, v = i - r * VPR;
            *(float4*)(Xbuf + r * XP + 4 * v) =
                *((const float4*)(X + (size_t)(rowbase + r) * DIN) + v);
        }
    }

    float cst[8][2];
#pragma unroll
    for (int r = 0; r < 8; r++) { cst[r][0] = 0.f; cst[r][1] = 0.f; }
    u64 acc[8][4];
    __syncthreads(); // bias/Waux/Xbuf(bcast) visible

    for (int t = 0; t < CT; ++t) {
        if (!BCAST) {
            constexpr int VPR = DIN / 4; // 15 or 32
            for (int i = tid; i < MR * VPR; i += NT) {
                int r = i / VPR, v = i - r * VPR;
                *(float4*)(Xbuf + r * XP + 4 * v) =
                    *((const float4*)(X + ((size_t)(rowbase + r) * CT + t) * DIN) + v);
            }
        }
        // acc init from bias (one u64 per gate, replicated to 8 rows)
        {
            const float* bb = bias_s + cb0;
#pragma unroll
            for (int j = 0; j < 4; j++) {
                u64 b = *(const u64*)(bb + 128 * j);
#pragma unroll
                for (int r = 0; r < 8; r++) acc[r][j] = b;
            }
        }

        gemm_pass<DIN, DBUF>(Wih, Xbuf + r0 * XP, XP, Wt0, Wt1, tid, cb0, acc);
        if (t > 0)
            gemm_pass<CH, DBUF>(Whh, Hbuf + r0 * CH, CH, Wt0, Wt1, tid, cb0, acc);
        __syncthreads(); // all reads of Hbuf/Xbuf done (needed for !DBUF path)

        // ---- cell update; thread h-cols = cb0 + {0,1} ----
#pragma unroll
        for (int r = 0; r < 8; r++) {
            float2 iv = unpack2(acc[r][0]);
            float2 fv = unpack2(acc[r][1]);
            float2 gv = unpack2(acc[r][2]);
            float2 ov = unpack2(acc[r][3]);
            float h0, h1;
            {
                float ig = sigf(iv.x), fg = sigf(fv.x);
                float gg = tanhfast(gv.x), og = sigf(ov.x);
                float cv = fmaf(fg, cst[r][0], ig * gg);
                cst[r][0] = cv;
                h0 = og * tanhfast(cv);
            }
            {
                float ig = sigf(iv.y), fg = sigf(fv.y);
                float gg = tanhfast(gv.y), og = sigf(ov.y);
                float cv = fmaf(fg, cst[r][1], ig * gg);
                cst[r][1] = cv;
                h1 = og * tanhfast(cv);
            }
            float2 h2 = make_float2(h0, h1);
            *(float2*)(Hbuf + (r0 + r) * CH + cb0) = h2;
            if (MODE == 0) {
                *(float2*)(OutSeq + ((size_t)(rowbase + r0 + r) * CT + t) * CH + cb0) = h2;
            }
        }

        if (MODE == 2) {
            __syncthreads(); // h_t complete in Hbuf
            // out_t[32][60] = h_t @ W_out^T + b_out ; r warp-uniform -> broadcast h,
            // Waux pitch 132 -> conflict-free float4 per 8-lane phase.
#pragma unroll
            for (int l = 0; l < 8; l++) {
                int i = tid + l * NT;
                int r = i >> 6, c = i & 63;
                if (c < CD) {
                    const float4* h4 = (const float4*)(Hbuf + r * CH);
                    const float4* w4 = (const float4*)(Waux_s + c * 132);
                    float sum = __ldg(baux + c);
#pragma unroll 8
                    for (int k4 = 0; k4 < 32; k4++) {
                        float4 hh = h4[k4], ww = w4[k4];
                        sum = fmaf(hh.x, ww.x, sum); sum = fmaf(hh.y, ww.y, sum);
                        sum = fmaf(hh.z, ww.z, sum); sum = fmaf(hh.w, ww.w, sum);
                    }
                    OutAux[((size_t)(rowbase + r) * CT + t) * CD + c] = sum;
                }
            }
            // next t's first pass barrier orders any Wt/Hbuf re-writes after this.
        }
    }

    if (MODE == 1) {
        // z[32][64] = h_last @ W_lat^T + b_lat ; stage W_lat at pitch 132 in Wt region
        __syncthreads();
        for (int i = tid; i < CL * CH; i += NT) {
            int c = i >> 7, k = i & 127;
            Wt0[c * 132 + k] = Waux[i]; // DBUF=1 -> 16384-float region, fits 64*132
        }
        __syncthreads();
#pragma unroll
        for (int l = 0; l < 8; l++) {
            int i = tid + l * NT;
            int r = i >> 6, c = i & 63;
            const float4* h4 = (const float4*)(Hbuf + r * CH);
            const float4* w4 = (const float4*)(Wt0 + c * 132);
            float sum = __ldg(baux + c);
#pragma unroll 8
            for (int k4 = 0; k4 < 32; k4++) {
                float4 hh = h4[k4], ww = w4[k4];
                sum = fmaf(hh.x, ww.x, sum); sum = fmaf(hh.y, ww.y, sum);
                sum = fmaf(hh.z, ww.z, sum); sum = fmaf(hh.w, ww.w, sum);
            }
            OutAux[(size_t)(rowbase + r) * CL + c] = sum;
        }
    }
}

// ----------------------------------------------------------------------------

extern "C" void kernel_launch(void* const* d_in, const int* in_sizes, int n_in,
                              void* d_out, int out_size)
{
    const float* x     = (const float*)d_in[0];
    const float* e0Wih = (const float*)d_in[1];
    const float* e0Whh = (const float*)d_in[2];
    const float* e0bih = (const float*)d_in[3];
    const float* e0bhh = (const float*)d_in[4];
    const float* e1Wih = (const float*)d_in[5];
    const float* e1Whh = (const float*)d_in[6];
    const float* e1bih = (const float*)d_in[7];
    const float* e1bhh = (const float*)d_in[8];
    const float* d0Wih = (const float*)d_in[9];
    const float* d0Whh = (const float*)d_in[10];
    const float* d0bih = (const float*)d_in[11];
    const float* d0bhh = (const float*)d_in[12];
    const float* d1Wih = (const float*)d_in[13];
    const float* d1Whh = (const float*)d_in[14];
    const float* d1bih = (const float*)d_in[15];
    const float* d1bhh = (const float*)d_in[16];
    const float* Wlat  = (const float*)d_in[17];
    const float* blat  = (const float*)d_in[18];
    const float* Wout  = (const float*)d_in[19];
    const float* bout  = (const float*)d_in[20];
    float* out = (float*)d_out;

    float *h1p, *d1p, *zp;
    cudaGetSymbolAddress((void**)&h1p, g_h1);
    cudaGetSymbolAddress((void**)&d1p, g_d1);
    cudaGetSymbolAddress((void**)&zp,  g_z);

    // smem (floats): Hbuf 4096 + Xbuf 32*XP + bias 512 + Wt (8192 or 16384) + MODE2 7920
    const int SM_ENC0 = (4096 + 32 * 60  + 512 + 16384) * 4;          // 91,648
    const int SM_ENC1 = (4096 + 32 * 128 + 512 + 16384) * 4;          // 100,352
    const int SM_DEC0 = (4096 + 32 * 64  + 512 + 16384) * 4;          // 92,160
    const int SM_DEC1 = (4096 + 32 * 128 + 512 + 8192 + 7920) * 4;    // 99,264

    cudaFuncSetAttribute((const void*)lstm_kernel<60, 0, 0, 1>,
                         cudaFuncAttributeMaxDynamicSharedMemorySize, SM_ENC0);
    cudaFuncSetAttribute((const void*)lstm_kernel<128, 1, 0, 1>,
                         cudaFuncAttributeMaxDynamicSharedMemorySize, SM_ENC1);
    cudaFuncSetAttribute((const void*)lstm_kernel<64, 0, 1, 1>,
                         cudaFuncAttributeMaxDynamicSharedMemorySize, SM_DEC0);
    cudaFuncSetAttribute((const void*)lstm_kernel<128, 2, 0, 0>,
                         cudaFuncAttributeMaxDynamicSharedMemorySize, SM_DEC1);

    dim3 grid(CB / MR); // 2048 CTAs

    // encoder layer 0: x [B,T,60] -> h1 seq [B,T,128]
    lstm_kernel<60, 0, 0, 1><<<grid, NT, SM_ENC0>>>(
        x, e0Wih, e0Whh, e0bih, e0bhh, nullptr, nullptr, h1p, nullptr);
    // encoder layer 1: h1 -> h_last -> z [B,64]
    lstm_kernel<128, 1, 0, 1><<<grid, NT, SM_ENC1>>>(
        h1p, e1Wih, e1Whh, e1bih, e1bhh, Wlat, blat, nullptr, zp);
    // decoder layer 0: z broadcast over T -> d1 seq [B,T,128]
    lstm_kernel<64, 0, 1, 1><<<grid, NT, SM_DEC0>>>(
        zp, d0Wih, d0Whh, d0bih, d0bhh, nullptr, nullptr, d1p, nullptr);
    // decoder layer 1 + output projection: d1 -> recon [B,T,60]
    lstm_kernel<128, 2, 0, 0><<<grid, NT, SM_DEC1>>>(
        d1p, d1Wih, d1Whh, d1bih, d1bhh, Wout, bout, nullptr, out);
}

// round 11
// speedup vs baseline: 1.4330x; 1.4330x over previous
#include <cuda_runtime.h>

// ----------------------------------------------------------------------------
// LSTM autoencoder, fp32, FFMA2 4x16 tile + PRE-TRANSPOSED WEIGHTS.
// B=65536, T=8, D=60, H=128, L=64. PyTorch gate order i,f,g,o.
//
// Round-10 finding: the in-loop weight transpose (scalar STS, 4-way bank
// conflicts, every 16-k chunk, every timestep) was the dominant smem-crossbar
// consumer. Fix: a tiny prologue kernel transposes all 8 weight matrices into
// WT[k][c] (pitch 512) in global scratch once per launch; the layer kernel's
// staging becomes a flat coalesced LDG.128 -> STS.128 copy (conflict-free).
//
// Per CTA: M=32 batch rows, 256 threads. Thread (tx,ty) owns rows r0..r0+3
// (r0=4*ty) and gate columns {4*tx+e + 128*j : e=0..3, j=0..3}; 32 packed
// f32x2 accumulators via fma.rn.f32x2. Weights read as conflict-free LDS.128
// (lane stride 16B); activations warp-broadcast float4. c-state in registers;
// h-state in smem. DBUF=1 double-buffers weight staging.
// MODE 0: write h sequence; MODE 1: z = h_last@W_lat^T+b; MODE 2: per-t
// projection out_t = h_t@W_out^T+b (conflict-free pitch-132 float4 epilogue).
// ----------------------------------------------------------------------------

typedef unsigned long long u64;

#define CB 65536
#define CT 8
#define CD 60
#define CH 128
#define CL 64
#define MR 32
#define NT 256

__device__ float g_h1[(size_t)CB * CT * CH]; // 256 MB
__device__ float g_d1[(size_t)CB * CT * CH]; // 256 MB
__device__ float g_z [(size_t)CB * CL];      // 16 MB
// transposed weights: 8 matrices, total (60+128+64+128 + 4*128) = 892 rows x 512
__device__ float g_wt[892 * 512];

__device__ __forceinline__ float sigf(float x)     { return 1.f / (1.f + __expf(-x)); }
__device__ __forceinline__ float tanhfast(float x) { return 2.f / (1.f + __expf(-2.f * x)) - 1.f; }

__device__ __forceinline__ void ffma2(u64& d, u64 a, u64 b) {
    asm("fma.rn.f32x2 %0, %1, %2, %0;" : "+l"(d) : "l"(a), "l"(b));
}
__device__ __forceinline__ u64 pack2(float x) {
    u64 v; asm("mov.b64 %0, {%1, %1};" : "=l"(v) : "f"(x)); return v;
}
__device__ __forceinline__ float2 unpack2(u64 v) {
    float2 f; asm("mov.b64 {%0, %1}, %2;" : "=f"(f.x), "=f"(f.y) : "l"(v)); return f;
}

// ---- prologue: WT[k*512 + c] = W[c*KD + k] (coalesced writes) ----
__global__ void transpose_w(const float* __restrict__ W, float* __restrict__ WT, int KD)
{
    int i = blockIdx.x * blockDim.x + threadIdx.x;
    if (i < KD * 512) {
        int k = i >> 9, c = i & 511;
        WT[i] = W[c * KD + k];
    }
}

// stage one 16-k chunk of WT [KD x 512] (k-major) into smem: flat coalesced copy.
template <int KD>
__device__ __forceinline__ void stage_chunkT(const float* __restrict__ WT, int ci,
                                             float* __restrict__ Wt, int tid)
{
    const int k0   = 16 * ci;
    const int klen = (KD - k0 < 16) ? (KD - k0) : 16;
    const float4* src = (const float4*)(WT + (size_t)k0 * 512);
    float4* dst = (float4*)Wt;
    const int n4 = klen * 128;
#pragma unroll
    for (int l = 0; l < 8; ++l) {
        int i = tid + l * NT;
        if (i < n4) dst[i] = src[i];
    }
}

// compute one staged chunk: act rows r0..r0+3 (this thread), nk4 groups of 4 k.
__device__ __forceinline__ void gemm_chunk2(const float* __restrict__ act, int pitch,
                                            const float* __restrict__ Wt, int tx,
                                            u64 (&acc)[4][8], int nk4)
{
    for (int q = 0; q < nk4; ++q) {
        float4 a0 = *(const float4*)(act + 4 * q);
        float4 a1 = *(const float4*)(act + pitch + 4 * q);
        float4 a2 = *(const float4*)(act + 2 * pitch + 4 * q);
        float4 a3 = *(const float4*)(act + 3 * pitch + 4 * q);
        const float* wb = Wt + q * 4 * 512 + 4 * tx;
#pragma unroll
        for (int v = 0; v < 4; ++v) {
            ulonglong2 w0 = *(const ulonglong2*)(wb + v * 512);
            ulonglong2 w1 = *(const ulonglong2*)(wb + v * 512 + 128);
            ulonglong2 w2 = *(const ulonglong2*)(wb + v * 512 + 256);
            ulonglong2 w3 = *(const ulonglong2*)(wb + v * 512 + 384);
            float s0 = (v == 0) ? a0.x : (v == 1) ? a0.y : (v == 2) ? a0.z : a0.w;
            float s1 = (v == 0) ? a1.x : (v == 1) ? a1.y : (v == 2) ? a1.z : a1.w;
            float s2 = (v == 0) ? a2.x : (v == 1) ? a2.y : (v == 2) ? a2.z : a2.w;
            float s3 = (v == 0) ? a3.x : (v == 1) ? a3.y : (v == 2) ? a3.z : a3.w;
            u64 p0 = pack2(s0), p1 = pack2(s1), p2 = pack2(s2), p3 = pack2(s3);
            ffma2(acc[0][0], p0, w0.x); ffma2(acc[0][1], p0, w0.y);
            ffma2(acc[0][2], p0, w1.x); ffma2(acc[0][3], p0, w1.y);
            ffma2(acc[0][4], p0, w2.x); ffma2(acc[0][5], p0, w2.y);
            ffma2(acc[0][6], p0, w3.x); ffma2(acc[0][7], p0, w3.y);
            ffma2(acc[1][0], p1, w0.x); ffma2(acc[1][1], p1, w0.y);
            ffma2(acc[1][2], p1, w1.x); ffma2(acc[1][3], p1, w1.y);
            ffma2(acc[1][4], p1, w2.x); ffma2(acc[1][5], p1, w2.y);
            ffma2(acc[1][6], p1, w3.x); ffma2(acc[1][7], p1, w3.y);
            ffma2(acc[2][0], p2, w0.x); ffma2(acc[2][1], p2, w0.y);
            ffma2(acc[2][2], p2, w1.x); ffma2(acc[2][3], p2, w1.y);
            ffma2(acc[2][4], p2, w2.x); ffma2(acc[2][5], p2, w2.y);
            ffma2(acc[2][6], p2, w3.x); ffma2(acc[2][7], p2, w3.y);
            ffma2(acc[3][0], p3, w0.x); ffma2(acc[3][1], p3, w0.y);
            ffma2(acc[3][2], p3, w1.x); ffma2(acc[3][3], p3, w1.y);
            ffma2(acc[3][4], p3, w2.x); ffma2(acc[3][5], p3, w2.y);
            ffma2(acc[3][6], p3, w3.x); ffma2(acc[3][7], p3, w3.y);
        }
    }
}

// one full GEMM pass over transposed weights WT [KD x 512] against act.
template <int KD, int DBUF>
__device__ __forceinline__ void gemm_pass(const float* __restrict__ WT,
                                          const float* __restrict__ act, int pitch,
                                          float* __restrict__ Wt0, float* __restrict__ Wt1,
                                          int tid, int tx, u64 (&acc)[4][8])
{
    constexpr int NCH = (KD + 15) >> 4;
    if (DBUF) {
        stage_chunkT<KD>(WT, 0, Wt0, tid);
        __syncthreads();
#pragma unroll
        for (int ci = 0; ci < NCH; ++ci) {
            float* cw = (ci & 1) ? Wt1 : Wt0;
            float* nw = (ci & 1) ? Wt0 : Wt1;
            if (ci + 1 < NCH) stage_chunkT<KD>(WT, ci + 1, nw, tid);
            const int klen = (KD - 16 * ci < 16) ? (KD - 16 * ci) : 16;
            gemm_chunk2(act + 16 * ci, pitch, cw, tx, acc, klen >> 2);
            __syncthreads();
        }
    } else {
#pragma unroll
        for (int ci = 0; ci < NCH; ++ci) {
            __syncthreads();                 // prior consumers of Wt0 done
            stage_chunkT<KD>(WT, ci, Wt0, tid);
            __syncthreads();
            const int klen = (KD - 16 * ci < 16) ? (KD - 16 * ci) : 16;
            gemm_chunk2(act + 16 * ci, pitch, Wt0, tx, acc, klen >> 2);
        }
    }
}

template <int DIN, int MODE, int BCAST, int DBUF>
__global__ __launch_bounds__(NT, 2)
void lstm_kernel(const float* __restrict__ X,
                 const float* __restrict__ WihT, const float* __restrict__ WhhT,
                 const float* __restrict__ bih, const float* __restrict__ bhh,
                 const float* __restrict__ Waux, const float* __restrict__ baux,
                 float* __restrict__ OutSeq, float* __restrict__ OutAux)
{
    constexpr int XP = (DIN + 3) & ~3;       // padded act pitch (60/64/128)
    extern __shared__ float sm[];
    float* Hbuf   = sm;                       // 4096
    float* Xbuf   = sm + 4096;                // 32*XP
    float* bias_s = Xbuf + MR * XP;           // 512
    float* Wt0    = bias_s + 512;             // 8192
    float* Wt1    = DBUF ? (Wt0 + 8192) : Wt0;
    float* Waux_s = Wt0 + (DBUF ? 16384 : 8192); // MODE2: 60*132 = 7920

    const int tid = threadIdx.x;
    const int tx  = tid & 31;
    const int ty  = tid >> 5;
    const int r0  = ty * 4;
    const int rowbase = blockIdx.x * MR;

    for (int i = tid; i < 512; i += NT) bias_s[i] = bih[i] + bhh[i];
    if (MODE == 2) {
        for (int i = tid; i < CD * CH; i += NT) {
            int c = i >> 7, k = i & 127;
            Waux_s[c * 132 + k] = Waux[i];
        }
    }
    if (BCAST) {
        constexpr int VPR = DIN / 4;
        for (int i = tid; i < MR * VPR; i += NT) {
            int r = i / VPR, v = i - r * VPR;
            *(float4*)(Xbuf + r * XP + 4 * v) =
                *((const float4*)(X + (size_t)(rowbase + r) * DIN) + v);
        }
    }

    float cst[16];
#pragma unroll
    for (int e = 0; e < 16; e++) cst[e] = 0.f;
    u64 acc[4][8];
    __syncthreads(); // bias/Waux/Xbuf(bcast) visible

    for (int t = 0; t < CT; ++t) {
        if (!BCAST) {
            constexpr int VPR = DIN / 4; // 15 or 32
            for (int i = tid; i < MR * VPR; i += NT) {
                int r = i / VPR, v = i - r * VPR;
                *(float4*)(Xbuf + r * XP + 4 * v) =
                    *((const float4*)(X + ((size_t)(rowbase + r) * CT + t) * DIN) + v);
            }
        }
        // acc init from bias (pairs)
        {
            const float* bb = bias_s + 4 * tx;
#pragma unroll
            for (int j = 0; j < 4; j++) {
                u64 b0 = *(const u64*)(bb + 128 * j);
                u64 b1 = *(const u64*)(bb + 128 * j + 2);
#pragma unroll
                for (int r = 0; r < 4; r++) { acc[r][2 * j] = b0; acc[r][2 * j + 1] = b1; }
            }
        }

        gemm_pass<DIN, DBUF>(WihT, Xbuf + r0 * XP, XP, Wt0, Wt1, tid, tx, acc);
        if (t > 0)
            gemm_pass<CH, DBUF>(WhhT, Hbuf + r0 * CH, CH, Wt0, Wt1, tid, tx, acc);
        __syncthreads(); // all reads of Hbuf/Xbuf done (needed for !DBUF path)

        // ---- cell update; thread cols = 4*tx+e of each gate ----
#pragma unroll
        for (int r = 0; r < 4; r++) {
            float2 i01 = unpack2(acc[r][0]), i23 = unpack2(acc[r][1]);
            float2 f01 = unpack2(acc[r][2]), f23 = unpack2(acc[r][3]);
            float2 g01 = unpack2(acc[r][4]), g23 = unpack2(acc[r][5]);
            float2 o01 = unpack2(acc[r][6]), o23 = unpack2(acc[r][7]);
            float iv[4] = { i01.x, i01.y, i23.x, i23.y };
            float fv[4] = { f01.x, f01.y, f23.x, f23.y };
            float gv[4] = { g01.x, g01.y, g23.x, g23.y };
            float ov[4] = { o01.x, o01.y, o23.x, o23.y };
            float hv[4];
#pragma unroll
            for (int e = 0; e < 4; e++) {
                float ig = sigf(iv[e]);
                float fg = sigf(fv[e]);
                float gg = tanhfast(gv[e]);
                float og = sigf(ov[e]);
                float cv = fmaf(fg, cst[r * 4 + e], ig * gg);
                cst[r * 4 + e] = cv;
                hv[e] = og * tanhfast(cv);
            }
            float4 h4 = make_float4(hv[0], hv[1], hv[2], hv[3]);
            *(float4*)(Hbuf + (r0 + r) * CH + 4 * tx) = h4;
            if (MODE == 0) {
                *(float4*)(OutSeq + ((size_t)(rowbase + r0 + r) * CT + t) * CH + 4 * tx) = h4;
            }
        }

        if (MODE == 2) {
            __syncthreads(); // h_t complete in Hbuf
            // out_t[32][60] = h_t @ W_out^T + b_out ; r warp-uniform -> broadcast h,
            // Waux pitch 132 -> conflict-free float4 per 8-lane phase.
#pragma unroll
            for (int l = 0; l < 8; l++) {
                int i = tid + l * NT;
                int r = i >> 6, c = i & 63;
                if (c < CD) {
                    const float4* h4 = (const float4*)(Hbuf + r * CH);
                    const float4* w4 = (const float4*)(Waux_s + c * 132);
                    float sum = __ldg(baux + c);
#pragma unroll 8
                    for (int k4 = 0; k4 < 32; k4++) {
                        float4 hh = h4[k4], ww = w4[k4];
                        sum = fmaf(hh.x, ww.x, sum); sum = fmaf(hh.y, ww.y, sum);
                        sum = fmaf(hh.z, ww.z, sum); sum = fmaf(hh.w, ww.w, sum);
                    }
                    OutAux[((size_t)(rowbase + r) * CT + t) * CD + c] = sum;
                }
            }
            // next t's first pass barrier orders any Wt/Hbuf re-writes after this.
        }
    }

    if (MODE == 1) {
        // z[32][64] = h_last @ W_lat^T + b_lat ; stage W_lat at pitch 132 in Wt region
        __syncthreads();
        for (int i = tid; i < CL * CH; i += NT) {
            int c = i >> 7, k = i & 127;
            Wt0[c * 132 + k] = Waux[i]; // DBUF=1 -> 16384-float region, fits 64*132
        }
        __syncthreads();
#pragma unroll
        for (int l = 0; l < 8; l++) {
            int i = tid + l * NT;
            int r = i >> 6, c = i & 63;
            const float4* h4 = (const float4*)(Hbuf + r * CH);
            const float4* w4 = (const float4*)(Wt0 + c * 132);
            float sum = __ldg(baux + c);
#pragma unroll 8
            for (int k4 = 0; k4 < 32; k4++) {
                float4 hh = h4[k4], ww = w4[k4];
                sum = fmaf(hh.x, ww.x, sum); sum = fmaf(hh.y, ww.y, sum);
                sum = fmaf(hh.z, ww.z, sum); sum = fmaf(hh.w, ww.w, sum);
            }
            OutAux[(size_t)(rowbase + r) * CL + c] = sum;
        }
    }
}

// ----------------------------------------------------------------------------

extern "C" void kernel_launch(void* const* d_in, const int* in_sizes, int n_in,
                              void* d_out, int out_size)
{
    const float* x     = (const float*)d_in[0];
    const float* e0Wih = (const float*)d_in[1];
    const float* e0Whh = (const float*)d_in[2];
    const float* e0bih = (const float*)d_in[3];
    const float* e0bhh = (const float*)d_in[4];
    const float* e1Wih = (const float*)d_in[5];
    const float* e1Whh = (const float*)d_in[6];
    const float* e1bih = (const float*)d_in[7];
    const float* e1bhh = (const float*)d_in[8];
    const float* d0Wih = (const float*)d_in[9];
    const float* d0Whh = (const float*)d_in[10];
    const float* d0bih = (const float*)d_in[11];
    const float* d0bhh = (const float*)d_in[12];
    const float* d1Wih = (const float*)d_in[13];
    const float* d1Whh = (const float*)d_in[14];
    const float* d1bih = (const float*)d_in[15];
    const float* d1bhh = (const float*)d_in[16];
    const float* Wlat  = (const float*)d_in[17];
    const float* blat  = (const float*)d_in[18];
    const float* Wout  = (const float*)d_in[19];
    const float* bout  = (const float*)d_in[20];
    float* out = (float*)d_out;

    float *h1p, *d1p, *zp, *wtp;
    cudaGetSymbolAddress((void**)&h1p, g_h1);
    cudaGetSymbolAddress((void**)&d1p, g_d1);
    cudaGetSymbolAddress((void**)&zp,  g_z);
    cudaGetSymbolAddress((void**)&wtp, g_wt);

    // WT region offsets (rows of 512)
    const int R_E0IH = 0;            // KD=60
    const int R_E0HH = 60;           // KD=128
    const int R_E1IH = 188;          // KD=128
    const int R_E1HH = 316;          // KD=128
    const int R_D0IH = 444;          // KD=64
    const int R_D0HH = 508;          // KD=128
    const int R_D1IH = 636;          // KD=128
    const int R_D1HH = 764;          // KD=128  (end 892)

    struct { const float* src; int off; int kd; } tw[8] = {
        { e0Wih, R_E0IH, 60  }, { e0Whh, R_E0HH, 128 },
        { e1Wih, R_E1IH, 128 }, { e1Whh, R_E1HH, 128 },
        { d0Wih, R_D0IH, 64  }, { d0Whh, R_D0HH, 128 },
        { d1Wih, R_D1IH, 128 }, { d1Whh, R_D1HH, 128 },
    };
    for (int m = 0; m < 8; ++m) {
        int n = tw[m].kd * 512;
        transpose_w<<<(n + 255) / 256, 256>>>(tw[m].src, wtp + (size_t)tw[m].off * 512,
                                              tw[m].kd);
    }

    // smem (floats): Hbuf 4096 + Xbuf 32*XP + bias 512 + Wt (8192 or 16384) + MODE2 7920
    const int SM_ENC0 = (4096 + 32 * 60  + 512 + 16384) * 4;          // 91,648
    const int SM_ENC1 = (4096 + 32 * 128 + 512 + 16384) * 4;          // 100,352
    const int SM_DEC0 = (4096 + 32 * 64  + 512 + 16384) * 4;          // 92,160
    const int SM_DEC1 = (4096 + 32 * 128 + 512 + 8192 + 7920) * 4;    // 99,264

    cudaFuncSetAttribute((const void*)lstm_kernel<60, 0, 0, 1>,
                         cudaFuncAttributeMaxDynamicSharedMemorySize, SM_ENC0);
    cudaFuncSetAttribute((const void*)lstm_kernel<128, 1, 0, 1>,
                         cudaFuncAttributeMaxDynamicSharedMemorySize, SM_ENC1);
    cudaFuncSetAttribute((const void*)lstm_kernel<64, 0, 1, 1>,
                         cudaFuncAttributeMaxDynamicSharedMemorySize, SM_DEC0);
    cudaFuncSetAttribute((const void*)lstm_kernel<128, 2, 0, 0>,
                         cudaFuncAttributeMaxDynamicSharedMemorySize, SM_DEC1);

    dim3 grid(CB / MR); // 2048 CTAs

    // encoder layer 0: x [B,T,60] -> h1 seq [B,T,128]
    lstm_kernel<60, 0, 0, 1><<<grid, NT, SM_ENC0>>>(
        x, wtp + (size_t)R_E0IH * 512, wtp + (size_t)R_E0HH * 512,
        e0bih, e0bhh, nullptr, nullptr, h1p, nullptr);
    // encoder layer 1: h1 -> h_last -> z [B,64]
    lstm_kernel<128, 1, 0, 1><<<grid, NT, SM_ENC1>>>(
        h1p, wtp + (size_t)R_E1IH * 512, wtp + (size_t)R_E1HH * 512,
        e1bih, e1bhh, Wlat, blat, nullptr, zp);
    // decoder layer 0: z broadcast over T -> d1 seq [B,T,128]
    lstm_kernel<64, 0, 1, 1><<<grid, NT, SM_DEC0>>>(
        zp, wtp + (size_t)R_D0IH * 512, wtp + (size_t)R_D0HH * 512,
        d0bih, d0bhh, nullptr, nullptr, d1p, nullptr);
    // decoder layer 1 + output projection: d1 -> recon [B,T,60]
    lstm_kernel<128, 2, 0, 0><<<grid, NT, SM_DEC1>>>(
        d1p, wtp + (size_t)R_D1IH * 512, wtp + (size_t)R_D1HH * 512,
        d1bih, d1bhh, Wout, bout, nullptr, out);
}